// round 15
// baseline (speedup 1.0000x reference)
#include <cuda_runtime.h>
#include <cuda_bf16.h>
#include <cstdint>

// ManeuverHead on GB300 — 2 kernels, raw mma.sync pipeline (R14 base +
// cache-policy segregation: streaming gather (.cs) vs pinned w1 fragments
// (L1::evict_last) so the gather stream stops thrashing the fragment table).
// N=262144, B=4096, D=128, G=8, R=7.

#define NNODES   262144
#define NB       4096
#define GG       8
#define RR       7
#define NSLOTS   (NB * GG)
#define NEGV     (-1e9f)
#define FGRID    256

// ---------------- device scratch ------------------------------------------
__device__ int          d_blockSums[FGRID];
__device__ int          d_blockOff[FGRID];
__device__ int          d_cbase[NB];
__device__ int          d_slotNode[NSLOTS];
__device__ uint2        d_w1frag[8192];   // 256 tiles (kt 0..15, nt 0..15) x 32 lanes
__device__ uint2        d_w2frag[256];    // 8 k-tiles x 32 lanes (w2 padded to 8 cols)
__device__ unsigned int g_cnt;            // zero-init
__device__ volatile unsigned int g_gen;   // zero-init

__device__ __forceinline__ unsigned int pk_bf2(float x, float y) {
    __nv_bfloat162 p = __floats2bfloat162_rn(x, y);
    return *reinterpret_cast<unsigned int*>(&p);
}

// streaming (evict-first) float4 load
__device__ __forceinline__ float4 ldg_cs4(const float4* p) {
    float4 v;
    asm volatile("ld.global.cs.v4.f32 {%0,%1,%2,%3}, [%4];"
                 : "=f"(v.x), "=f"(v.y), "=f"(v.z), "=f"(v.w) : "l"(p));
    return v;
}
// L1-pinned (evict-last) uint2 load
__device__ __forceinline__ uint2 ldg_el2(const uint2* p) {
    uint2 v;
    asm volatile("ld.global.L1::evict_last.v2.u32 {%0,%1}, [%2];"
                 : "=r"(v.x), "=r"(v.y) : "l"(p));
    return v;
}
__device__ __forceinline__ float2 ldg_el_f2(const float* p) {
    float2 v;
    asm volatile("ld.global.L1::evict_last.v2.f32 {%0,%1}, [%2];"
                 : "=f"(v.x), "=f"(v.y) : "l"(p));
    return v;
}
__device__ __forceinline__ int ldg_cs1(const int* p) {
    int v;
    asm volatile("ld.global.cs.s32 %0, [%1];" : "=r"(v) : "l"(p));
    return v;
}
__device__ __forceinline__ void stg_cs1(float* p, float v) {
    asm volatile("st.global.cs.f32 [%0], %1;" :: "l"(p), "f"(v));
}

// ---------------- K1: fused front end --------------------------------------
__global__ void __launch_bounds__(256)
k_front(const int* __restrict__ mask, const int* __restrict__ batch,
        const float* __restrict__ w1, const float* __restrict__ w2) {
    int t = threadIdx.x, bid = blockIdx.x;
    int lane = t & 31, warp = t >> 5;
    int gid = bid * 256 + t;

    __shared__ int ws[8];
    __shared__ unsigned int s_gen;
    __shared__ int s_lead;

    // ---- P0: aux init + fragment-order weight staging ----
    if (gid < NSLOTS) d_slotNode[gid] = -1;
    if (gid < 8192) {                       // w1 fragments (m16n8k16 B layout)
        int tile = gid >> 5, fl = gid & 31;
        int kt = tile >> 4, nt = tile & 15;
        int q = fl & 3, g = fl >> 2;
        int k0 = kt * 16 + 2 * q;
        int n  = nt * 8 + g;
        uint2 v;
        v.x = pk_bf2(w1[k0 * 128 + n],        w1[(k0 + 1) * 128 + n]);
        v.y = pk_bf2(w1[(k0 + 8) * 128 + n],  w1[(k0 + 9) * 128 + n]);
        d_w1frag[gid] = v;
    }
    if (gid < 256) {                        // w2 fragments (padded to 8 cols)
        int kt2 = gid >> 5, fl = gid & 31;
        int q = fl & 3, g = fl >> 2;
        int k0 = kt2 * 16 + 2 * q;
        float w00 = (g < RR) ? w2[k0 * RR + g]       : 0.f;
        float w01 = (g < RR) ? w2[(k0 + 1) * RR + g] : 0.f;
        float w10 = (g < RR) ? w2[(k0 + 8) * RR + g] : 0.f;
        float w11 = (g < RR) ? w2[(k0 + 9) * RR + g] : 0.f;
        uint2 v;
        v.x = pk_bf2(w00, w01);
        v.y = pk_bf2(w10, w11);
        d_w2frag[gid] = v;
    }

    // ---- P0: block scan of masked flags ----
    int4 m = ((const int4*)mask)[gid];
    int4 b = ((const int4*)batch)[gid];
    int g0 = m.x != 0, g1 = m.y != 0, g2 = m.z != 0, g3 = m.w != 0;
    int s = g0 + g1 + g2 + g3;
    int inc = s;
#pragma unroll
    for (int o = 1; o < 32; o <<= 1) {
        int v = __shfl_up_sync(~0u, inc, o);
        if (lane >= o) inc += v;
    }
    if (lane == 31) ws[warp] = inc;
    __syncthreads();
    if (warp == 0 && lane < 8) {
        int v = ws[lane], iv = v;
#pragma unroll
        for (int o = 1; o < 8; o <<= 1) {
            int x = __shfl_up_sync(0xffu, iv, o);
            if (lane >= o) iv += x;
        }
        ws[lane] = iv - v;
        if (lane == 7) d_blockSums[bid] = iv;
    }
    __syncthreads();
    int lexcl = ws[warp] + (inc - s);

    // ---- BAR1: leader scans blockSums -> blockOff ----
    __threadfence();
    __syncthreads();
    if (t == 0) {
        s_gen = g_gen;
        unsigned int a = atomicAdd(&g_cnt, 1u);
        s_lead = (a == (unsigned)gridDim.x - 1u);
    }
    __syncthreads();
    if (s_lead) {
        __threadfence();
        int v = d_blockSums[t];
        int iv = v;
#pragma unroll
        for (int o = 1; o < 32; o <<= 1) {
            int x = __shfl_up_sync(~0u, iv, o);
            if (lane >= o) iv += x;
        }
        if (lane == 31) ws[warp] = iv;
        __syncthreads();
        if (warp == 0 && lane < 8) {
            int v2 = ws[lane], iv2 = v2;
#pragma unroll
            for (int o = 1; o < 8; o <<= 1) {
                int x = __shfl_up_sync(0xffu, iv2, o);
                if (lane >= o) iv2 += x;
            }
            ws[lane] = iv2 - v2;
        }
        __syncthreads();
        d_blockOff[t] = ws[warp] + (iv - v);
        __threadfence();
        __syncthreads();
        if (t == 0) {
            *(volatile unsigned int*)&g_cnt = 0u;
            __threadfence();
            g_gen = s_gen + 1u;
        }
    } else {
        if (t == 0) {
            while (g_gen == s_gen) __nanosleep(64);
            __threadfence();
        }
        __syncthreads();
    }

    // ---- P2: boundary nodes write cbase ----
    int pe0 = d_blockOff[bid] + lexcl;
    int pw = __shfl_up_sync(~0u, b.w, 1);
    int prevb = (lane == 0) ? ((gid > 0) ? batch[gid * 4 - 1] : -1) : pw;
    {
        int pe = pe0;
        if (b.x != prevb) d_cbase[b.x] = pe;  pe += g0;
        if (b.y != b.x)   d_cbase[b.y] = pe;  pe += g1;
        if (b.z != b.y)   d_cbase[b.z] = pe;  pe += g2;
        if (b.w != b.z)   d_cbase[b.w] = pe;
    }

    // ---- BAR2 ----
    __threadfence();
    __syncthreads();
    if (t == 0) {
        s_gen = g_gen;
        unsigned int a = atomicAdd(&g_cnt, 1u);
        s_lead = (a == (unsigned)gridDim.x - 1u);
    }
    __syncthreads();
    if (s_lead) {
        if (t == 0) {
            *(volatile unsigned int*)&g_cnt = 0u;
            __threadfence();
            g_gen = s_gen + 1u;
        }
        __syncthreads();
    } else {
        if (t == 0) {
            while (g_gen == s_gen) __nanosleep(64);
            __threadfence();
        }
        __syncthreads();
    }

    // ---- P3: scatter ----
    int base = gid * 4;
    int pre = pe0;
    if (g0) { int r = pre - d_cbase[b.x]; if (r < GG) d_slotNode[b.x * GG + r] = base;     pre++; }
    if (g1) { int r = pre - d_cbase[b.y]; if (r < GG) d_slotNode[b.y * GG + r] = base + 1; pre++; }
    if (g2) { int r = pre - d_cbase[b.z]; if (r < GG) d_slotNode[b.z * GG + r] = base + 2; pre++; }
    if (g3) { int r = pre - d_cbase[b.w]; if (r < GG) d_slotNode[b.w * GG + r] = base + 3; }
}

// ---------------- K2: main — warp-autonomous mma.sync pipeline --------------
// 512 blocks x 128 threads (4 warps). Warp strip: 16 rows x 264 bf16 (528 B
// row stride -> ldmatrix conflict-free), cols 0..127 node feats, 128..255
// globals. Gather uses streaming loads; w1/w2 fragments pinned in L1.
#define STRIP_BYTES 8448
#define MAIN_SMEM_BYTES (4 * STRIP_BYTES)

__device__ __forceinline__ void mma16816(float& c0, float& c1, float& c2, float& c3,
                                         unsigned a0, unsigned a1, unsigned a2, unsigned a3,
                                         unsigned b0, unsigned b1) {
    asm volatile(
        "mma.sync.aligned.m16n8k16.row.col.f32.bf16.bf16.f32 "
        "{%0,%1,%2,%3}, {%4,%5,%6,%7}, {%8,%9}, {%0,%1,%2,%3};"
        : "+f"(c0), "+f"(c1), "+f"(c2), "+f"(c3)
        : "r"(a0), "r"(a1), "r"(a2), "r"(a3), "r"(b0), "r"(b1));
}

__global__ void __launch_bounds__(128, 4)
k_main(const float* __restrict__ nf,
       const float* __restrict__ gf,
       const float* __restrict__ b1,
       const float* __restrict__ b2,
       const int* __restrict__ mvm,
       float* __restrict__ out) {
    extern __shared__ __align__(16) unsigned char sm[];
    int t = threadIdx.x, w = t >> 5, lane = t & 31;
    unsigned char* strip = sm + w * STRIP_BYTES;

    int slot0 = (blockIdx.x * 4 + w) * 16;
    int b0w   = (blockIdx.x * 4 + w) * 2;          // 2 batches per warp

    int nd = (lane < 16) ? ldg_cs1(d_slotNode + slot0 + lane) : -1;

    // ---- gather: 16 rows x 64 float4-units, two 16-deep load batches,
    //      streaming (.cs) so the node stream never thrashes L1 ----
    {
        const float4* nf4 = (const float4*)nf;
        const float4* gf4 = (const float4*)gf;
        const float4 z = make_float4(0.f, 0.f, 0.f, 0.f);
#pragma unroll
        for (int bb = 0; bb < 2; bb++) {
            float4 v[16];
#pragma unroll
            for (int j = 0; j < 16; j++) {
                int i = lane + (bb * 16 + j) * 32;
                int row = i >> 6, c4 = i & 63;
                if (c4 < 32) {
                    int ndr = __shfl_sync(~0u, nd, row);
                    v[j] = (ndr >= 0) ? ldg_cs4(nf4 + ndr * 32 + c4) : z;
                } else {
                    v[j] = ldg_cs4(gf4 + (b0w + (row >> 3)) * 32 + (c4 - 32));
                }
            }
#pragma unroll
            for (int j = 0; j < 16; j++) {
                int i = lane + (bb * 16 + j) * 32;
                int row = i >> 6, c4 = i & 63;
                uint2 pk;
                pk.x = pk_bf2(v[j].x, v[j].y);
                pk.y = pk_bf2(v[j].z, v[j].w);
                *(uint2*)(strip + row * 528 + c4 * 8) = pk;
            }
        }
    }
    __syncwarp();

    // ---- layer 1: C[nt] (nt=0..15) = A(16x256) @ w1 fragments ----
    unsigned int smaddr;
    asm("{ .reg .u64 tt; cvta.to.shared.u64 tt, %1; cvt.u32.u64 %0, tt; }"
        : "=r"(smaddr) : "l"(strip));
    unsigned int lmrow = (lane & 7) + ((lane >> 3) & 1) * 8;
    unsigned int lmaddr = smaddr + lmrow * 528 + (lane >> 4) * 16;

    float c[16][4];
#pragma unroll
    for (int nt = 0; nt < 16; nt++)
#pragma unroll
        for (int j = 0; j < 4; j++) c[nt][j] = 0.f;

#pragma unroll 1
    for (int kt = 0; kt < 16; kt++) {
        unsigned a0, a1, a2, a3;
        asm volatile("ldmatrix.sync.aligned.m8n8.x4.shared.b16 {%0,%1,%2,%3}, [%4];"
                     : "=r"(a0), "=r"(a1), "=r"(a2), "=r"(a3)
                     : "r"(lmaddr + kt * 32));
        const uint2* fb = d_w1frag + kt * 16 * 32 + lane;
#pragma unroll
        for (int nt = 0; nt < 16; nt++) {
            uint2 bv = ldg_el2(fb + nt * 32);
            mma16816(c[nt][0], c[nt][1], c[nt][2], c[nt][3],
                     a0, a1, a2, a3, bv.x, bv.y);
        }
    }

    // ---- layer 2: in-register relu+b1 -> bf16 A fragments -> mma ----
    int q = lane & 3, g = lane >> 2;
    float d0 = 0.f, d1 = 0.f, d2 = 0.f, d3 = 0.f;
#pragma unroll
    for (int k2 = 0; k2 < 8; k2++) {
        float2 ba = ldg_el_f2(b1 + k2 * 16 + 2 * q);
        float2 bb = ldg_el_f2(b1 + k2 * 16 + 8 + 2 * q);
        unsigned A0 = pk_bf2(fmaxf(c[2 * k2][0] + ba.x, 0.f),
                             fmaxf(c[2 * k2][1] + ba.y, 0.f));
        unsigned A1 = pk_bf2(fmaxf(c[2 * k2][2] + ba.x, 0.f),
                             fmaxf(c[2 * k2][3] + ba.y, 0.f));
        unsigned A2 = pk_bf2(fmaxf(c[2 * k2 + 1][0] + bb.x, 0.f),
                             fmaxf(c[2 * k2 + 1][1] + bb.y, 0.f));
        unsigned A3 = pk_bf2(fmaxf(c[2 * k2 + 1][2] + bb.x, 0.f),
                             fmaxf(c[2 * k2 + 1][3] + bb.y, 0.f));
        uint2 bv = ldg_el2(d_w2frag + k2 * 32 + lane);
        mma16816(d0, d1, d2, d3, A0, A1, A2, A3, bv.x, bv.y);
    }

    // ---- masked output: fc2 c0,c1 = row g cols 2q,2q+1; c2,c3 = row g+8 ----
    {
        int r0c = 2 * q, r1c = 2 * q + 1;
        float b2v0 = b2[r0c];                       // r0c in {0,2,4,6} < 7
        float b2v1 = (r1c < RR) ? b2[r1c] : 0.f;
#pragma unroll
        for (int half = 0; half < 2; half++) {
            int m = g + half * 8;
            float v0 = half ? d2 : d0;
            float v1 = half ? d3 : d1;
            int occ = __shfl_sync(~0u, nd, m) >= 0;
            int bb2 = b0w + (m >> 3);
            int orow = bb2 * (GG * RR) + (m & 7) * RR;
            float o0 = (occ && ldg_cs1(mvm + orow + r0c) != 0) ? v0 + b2v0 : NEGV;
            stg_cs1(out + orow + r0c, o0);
            if (r1c < RR) {
                float o1 = (occ && ldg_cs1(mvm + orow + r1c) != 0) ? v1 + b2v1 : NEGV;
                stg_cs1(out + orow + r1c, o1);
            }
        }
    }
}

// ---------------- launch ---------------------------------------------------
extern "C" void kernel_launch(void* const* d_in, const int* in_sizes, int n_in,
                              void* d_out, int out_size) {
    const float* nf    = (const float*)d_in[0];
    const float* gf    = (const float*)d_in[1];
    const int*   gmask = (const int*)d_in[2];
    const int*   mvm   = (const int*)d_in[3];
    const int*   batch = (const int*)d_in[4];
    const float* w1    = (const float*)d_in[5];
    const float* b1    = (const float*)d_in[6];
    const float* w2    = (const float*)d_in[7];
    const float* b2    = (const float*)d_in[8];
    float*       out   = (float*)d_out;

    cudaFuncSetAttribute(k_main, cudaFuncAttributeMaxDynamicSharedMemorySize,
                         MAIN_SMEM_BYTES);

    k_front<<<FGRID, 256>>>(gmask, batch, w1, w2);
    k_main<<<512, 128, MAIN_SMEM_BYTES>>>(nf, gf, b1, b2, mvm, out);
}

// round 16
// speedup vs baseline: 1.0111x; 1.0111x over previous
#include <cuda_runtime.h>
#include <cuda_bf16.h>
#include <cstdint>

// ManeuverHead on GB300 — 2 kernels, raw mma.sync pipeline.
//  k_front: persistent fused front end (grid barriers): init + masked scans +
//           boundary cbase + scatter + w1/w2 fragment staging + P4: dedup'd
//           gpart GEMM (gpart[4096][128] = gf @ w1[128:] + b1, bf16 mma).
//  k_main : 512 blocks x 128 threads; each warp owns 16 slots (2 batches):
//           gather node half (16 LDG.128/lane) -> ldmatrix -> 128x
//           mma.m16n8k16 (K=128) -> epilogue adds gpart[batch] + relu in
//           registers -> layer-2 mma -> masked STG. No __syncthreads.
// N=262144, B=4096, D=128, G=8, R=7.

#define NNODES   262144
#define NB       4096
#define GG       8
#define RR       7
#define NSLOTS   (NB * GG)
#define NEGV     (-1e9f)
#define FGRID    256

// ---------------- device scratch ------------------------------------------
__device__ int          d_blockSums[FGRID];
__device__ int          d_blockOff[FGRID];
__device__ int          d_cbase[NB];
__device__ int          d_slotNode[NSLOTS];
__device__ uint2        d_w1frag[8192];   // 256 tiles (kt 0..15, nt 0..15) x 32 lanes
__device__ uint2        d_w2frag[256];    // 8 k-tiles x 32 lanes (w2 padded to 8 cols)
__device__ float        d_gpart[NB * 128];// gf @ w1[128:] + b1, fp32
__device__ unsigned int g_cnt;            // zero-init
__device__ volatile unsigned int g_gen;   // zero-init

__device__ __forceinline__ unsigned int pk_bf2(float x, float y) {
    __nv_bfloat162 p = __floats2bfloat162_rn(x, y);
    return *reinterpret_cast<unsigned int*>(&p);
}

__device__ __forceinline__ void mma16816(float& c0, float& c1, float& c2, float& c3,
                                         unsigned a0, unsigned a1, unsigned a2, unsigned a3,
                                         unsigned b0, unsigned b1) {
    asm volatile(
        "mma.sync.aligned.m16n8k16.row.col.f32.bf16.bf16.f32 "
        "{%0,%1,%2,%3}, {%4,%5,%6,%7}, {%8,%9}, {%0,%1,%2,%3};"
        : "+f"(c0), "+f"(c1), "+f"(c2), "+f"(c3)
        : "r"(a0), "r"(a1), "r"(a2), "r"(a3), "r"(b0), "r"(b1));
}

// ---------------- K1: fused front end --------------------------------------
__global__ void __launch_bounds__(256)
k_front(const int* __restrict__ mask, const int* __restrict__ batch,
        const float* __restrict__ w1, const float* __restrict__ w2,
        const float* __restrict__ b1, const float* __restrict__ gf) {
    int t = threadIdx.x, bid = blockIdx.x;
    int lane = t & 31, warp = t >> 5;
    int gid = bid * 256 + t;

    __shared__ int ws[8];
    __shared__ unsigned int s_gen;
    __shared__ int s_lead;

    // ---- P0: aux init + fragment-order weight staging ----
    if (gid < NSLOTS) d_slotNode[gid] = -1;
    if (gid < 8192) {                       // w1 fragments (m16n8k16 B layout)
        int tile = gid >> 5, fl = gid & 31;
        int kt = tile >> 4, nt = tile & 15;
        int q = fl & 3, g = fl >> 2;
        int k0 = kt * 16 + 2 * q;
        int n  = nt * 8 + g;
        uint2 v;
        v.x = pk_bf2(w1[k0 * 128 + n],        w1[(k0 + 1) * 128 + n]);
        v.y = pk_bf2(w1[(k0 + 8) * 128 + n],  w1[(k0 + 9) * 128 + n]);
        d_w1frag[gid] = v;
    }
    if (gid < 256) {                        // w2 fragments (padded to 8 cols)
        int kt2 = gid >> 5, fl = gid & 31;
        int q = fl & 3, g = fl >> 2;
        int k0 = kt2 * 16 + 2 * q;
        float w00 = (g < RR) ? w2[k0 * RR + g]       : 0.f;
        float w01 = (g < RR) ? w2[(k0 + 1) * RR + g] : 0.f;
        float w10 = (g < RR) ? w2[(k0 + 8) * RR + g] : 0.f;
        float w11 = (g < RR) ? w2[(k0 + 9) * RR + g] : 0.f;
        uint2 v;
        v.x = pk_bf2(w00, w01);
        v.y = pk_bf2(w10, w11);
        d_w2frag[gid] = v;
    }

    // ---- P0: block scan of masked flags ----
    int4 m = ((const int4*)mask)[gid];
    int4 b = ((const int4*)batch)[gid];
    int g0 = m.x != 0, g1 = m.y != 0, g2 = m.z != 0, g3 = m.w != 0;
    int s = g0 + g1 + g2 + g3;
    int inc = s;
#pragma unroll
    for (int o = 1; o < 32; o <<= 1) {
        int v = __shfl_up_sync(~0u, inc, o);
        if (lane >= o) inc += v;
    }
    if (lane == 31) ws[warp] = inc;
    __syncthreads();
    if (warp == 0 && lane < 8) {
        int v = ws[lane], iv = v;
#pragma unroll
        for (int o = 1; o < 8; o <<= 1) {
            int x = __shfl_up_sync(0xffu, iv, o);
            if (lane >= o) iv += x;
        }
        ws[lane] = iv - v;
        if (lane == 7) d_blockSums[bid] = iv;
    }
    __syncthreads();
    int lexcl = ws[warp] + (inc - s);

    // ---- BAR1: leader scans blockSums -> blockOff ----
    __threadfence();
    __syncthreads();
    if (t == 0) {
        s_gen = g_gen;
        unsigned int a = atomicAdd(&g_cnt, 1u);
        s_lead = (a == (unsigned)gridDim.x - 1u);
    }
    __syncthreads();
    if (s_lead) {
        __threadfence();
        int v = d_blockSums[t];
        int iv = v;
#pragma unroll
        for (int o = 1; o < 32; o <<= 1) {
            int x = __shfl_up_sync(~0u, iv, o);
            if (lane >= o) iv += x;
        }
        if (lane == 31) ws[warp] = iv;
        __syncthreads();
        if (warp == 0 && lane < 8) {
            int v2 = ws[lane], iv2 = v2;
#pragma unroll
            for (int o = 1; o < 8; o <<= 1) {
                int x = __shfl_up_sync(0xffu, iv2, o);
                if (lane >= o) iv2 += x;
            }
            ws[lane] = iv2 - v2;
        }
        __syncthreads();
        d_blockOff[t] = ws[warp] + (iv - v);
        __threadfence();
        __syncthreads();
        if (t == 0) {
            *(volatile unsigned int*)&g_cnt = 0u;
            __threadfence();
            g_gen = s_gen + 1u;
        }
    } else {
        if (t == 0) {
            while (g_gen == s_gen) __nanosleep(64);
            __threadfence();
        }
        __syncthreads();
    }

    // ---- P2: boundary nodes write cbase ----
    int pe0 = d_blockOff[bid] + lexcl;
    int pw = __shfl_up_sync(~0u, b.w, 1);
    int prevb = (lane == 0) ? ((gid > 0) ? batch[gid * 4 - 1] : -1) : pw;
    {
        int pe = pe0;
        if (b.x != prevb) d_cbase[b.x] = pe;  pe += g0;
        if (b.y != b.x)   d_cbase[b.y] = pe;  pe += g1;
        if (b.z != b.y)   d_cbase[b.z] = pe;  pe += g2;
        if (b.w != b.z)   d_cbase[b.w] = pe;
    }

    // ---- BAR2 ----
    __threadfence();
    __syncthreads();
    if (t == 0) {
        s_gen = g_gen;
        unsigned int a = atomicAdd(&g_cnt, 1u);
        s_lead = (a == (unsigned)gridDim.x - 1u);
    }
    __syncthreads();
    if (s_lead) {
        if (t == 0) {
            *(volatile unsigned int*)&g_cnt = 0u;
            __threadfence();
            g_gen = s_gen + 1u;
        }
        __syncthreads();
    } else {
        if (t == 0) {
            while (g_gen == s_gen) __nanosleep(64);
            __threadfence();
        }
        __syncthreads();
    }

    // ---- P3: scatter ----
    int base = gid * 4;
    int pre = pe0;
    if (g0) { int r = pre - d_cbase[b.x]; if (r < GG) d_slotNode[b.x * GG + r] = base;     pre++; }
    if (g1) { int r = pre - d_cbase[b.y]; if (r < GG) d_slotNode[b.y * GG + r] = base + 1; pre++; }
    if (g2) { int r = pre - d_cbase[b.z]; if (r < GG) d_slotNode[b.z * GG + r] = base + 2; pre++; }
    if (g3) { int r = pre - d_cbase[b.w]; if (r < GG) d_slotNode[b.w * GG + r] = base + 3; }

    // ---- P4: gpart GEMM — gpart = gf @ w1[128:256] + b1 (bf16 mma) ----
    // 2048 warps; warp gw: batch tile (gw>>3, 16 rows), n-tiles {2s, 2s+1}.
    // d_w1frag was written in P0 by all blocks; BAR1+BAR2 fences order it.
    {
        int gw = bid * 8 + warp;
        int tile = gw >> 3, sub = gw & 7;
        int b0g = tile * 16;
        int q = lane & 3, g = lane >> 2;
        const float* gfA = gf + b0g * 128;

        float cg[2][4];
#pragma unroll
        for (int j = 0; j < 2; j++)
#pragma unroll
            for (int k = 0; k < 4; k++) cg[j][k] = 0.f;

#pragma unroll
        for (int kt = 0; kt < 8; kt++) {
            int col = kt * 16 + 2 * q;
            float2 v0 = *(const float2*)(gfA + g * 128 + col);
            float2 v1 = *(const float2*)(gfA + (g + 8) * 128 + col);
            float2 v2 = *(const float2*)(gfA + g * 128 + col + 8);
            float2 v3 = *(const float2*)(gfA + (g + 8) * 128 + col + 8);
            unsigned a0 = pk_bf2(v0.x, v0.y);
            unsigned a1 = pk_bf2(v1.x, v1.y);
            unsigned a2 = pk_bf2(v2.x, v2.y);
            unsigned a3 = pk_bf2(v3.x, v3.y);
#pragma unroll
            for (int j = 0; j < 2; j++) {
                int nt = sub * 2 + j;
                uint2 bv = d_w1frag[(8 + kt) * 512 + nt * 32 + lane];
                mma16816(cg[j][0], cg[j][1], cg[j][2], cg[j][3],
                         a0, a1, a2, a3, bv.x, bv.y);
            }
        }
#pragma unroll
        for (int j = 0; j < 2; j++) {
            int nt = sub * 2 + j;
            float2 bv = *(const float2*)(b1 + nt * 8 + 2 * q);
            float2 s0 = make_float2(cg[j][0] + bv.x, cg[j][1] + bv.y);
            float2 s1 = make_float2(cg[j][2] + bv.x, cg[j][3] + bv.y);
            *(float2*)(d_gpart + (b0g + g) * 128 + nt * 8 + 2 * q)       = s0;
            *(float2*)(d_gpart + (b0g + g + 8) * 128 + nt * 8 + 2 * q)   = s1;
        }
    }
}

// ---------------- K2: main — warp-autonomous mma.sync pipeline --------------
// 512 blocks x 128 threads (4 warps). Warp strip: 16 rows x 136 bf16 (272 B
// row stride -> ldmatrix conflict-free), node-feature half only (K=128).
#define STRIP_BYTES 4352
#define MAIN_SMEM_BYTES (4 * STRIP_BYTES)

__global__ void __launch_bounds__(128, 4)
k_main(const float* __restrict__ nf,
       const float* __restrict__ b2,
       const int* __restrict__ mvm,
       float* __restrict__ out) {
    extern __shared__ __align__(16) unsigned char sm[];
    int t = threadIdx.x, w = t >> 5, lane = t & 31;
    unsigned char* strip = sm + w * STRIP_BYTES;

    int slot0 = (blockIdx.x * 4 + w) * 16;
    int b0w   = (blockIdx.x * 4 + w) * 2;          // 2 batches per warp

    int nd = (lane < 16) ? d_slotNode[slot0 + lane] : -1;

    // ---- gather: 16 rows x 32 float4-units (node half), 16-deep MLP ----
    {
        const float4* nf4 = (const float4*)nf;
        const float4 z = make_float4(0.f, 0.f, 0.f, 0.f);
        float4 v[16];
#pragma unroll
        for (int j = 0; j < 16; j++) {
            int ndr = __shfl_sync(~0u, nd, j);
            v[j] = (ndr >= 0) ? nf4[ndr * 32 + lane] : z;
        }
#pragma unroll
        for (int j = 0; j < 16; j++) {
            uint2 pk;
            pk.x = pk_bf2(v[j].x, v[j].y);
            pk.y = pk_bf2(v[j].z, v[j].w);
            *(uint2*)(strip + j * 272 + lane * 8) = pk;
        }
    }
    __syncwarp();

    // ---- layer 1: C[nt] (nt=0..15) = A(16x128) @ w1[0:128] fragments ----
    unsigned int smaddr;
    asm("{ .reg .u64 tt; cvta.to.shared.u64 tt, %1; cvt.u32.u64 %0, tt; }"
        : "=r"(smaddr) : "l"(strip));
    unsigned int lmrow = (lane & 7) + ((lane >> 3) & 1) * 8;
    unsigned int lmaddr = smaddr + lmrow * 272 + (lane >> 4) * 16;

    float c[16][4];
#pragma unroll
    for (int nt = 0; nt < 16; nt++)
#pragma unroll
        for (int j = 0; j < 4; j++) c[nt][j] = 0.f;

#pragma unroll 1
    for (int kt = 0; kt < 8; kt++) {
        unsigned a0, a1, a2, a3;
        asm volatile("ldmatrix.sync.aligned.m8n8.x4.shared.b16 {%0,%1,%2,%3}, [%4];"
                     : "=r"(a0), "=r"(a1), "=r"(a2), "=r"(a3)
                     : "r"(lmaddr + kt * 32));
        const uint2* fb = d_w1frag + kt * 512 + lane;
#pragma unroll
        for (int nt = 0; nt < 16; nt++) {
            uint2 bv = fb[nt * 32];
            mma16816(c[nt][0], c[nt][1], c[nt][2], c[nt][3],
                     a0, a1, a2, a3, bv.x, bv.y);
        }
    }

    // ---- layer 2: in-register relu(c + gpart) -> bf16 A fragments -> mma ----
    int q = lane & 3, g = lane >> 2;
    const float* gpA = d_gpart + b0w * 128;        // batch of rows g (0..7)
    const float* gpB = gpA + 128;                  // batch of rows g+8
    float d0 = 0.f, d1 = 0.f, d2 = 0.f, d3 = 0.f;
#pragma unroll
    for (int k2 = 0; k2 < 8; k2++) {
        int col = k2 * 16 + 2 * q;
        float2 gA0 = *(const float2*)(gpA + col);
        float2 gB0 = *(const float2*)(gpB + col);
        float2 gA1 = *(const float2*)(gpA + col + 8);
        float2 gB1 = *(const float2*)(gpB + col + 8);
        unsigned A0 = pk_bf2(fmaxf(c[2 * k2][0] + gA0.x, 0.f),
                             fmaxf(c[2 * k2][1] + gA0.y, 0.f));
        unsigned A1 = pk_bf2(fmaxf(c[2 * k2][2] + gB0.x, 0.f),
                             fmaxf(c[2 * k2][3] + gB0.y, 0.f));
        unsigned A2 = pk_bf2(fmaxf(c[2 * k2 + 1][0] + gA1.x, 0.f),
                             fmaxf(c[2 * k2 + 1][1] + gA1.y, 0.f));
        unsigned A3 = pk_bf2(fmaxf(c[2 * k2 + 1][2] + gB1.x, 0.f),
                             fmaxf(c[2 * k2 + 1][3] + gB1.y, 0.f));
        uint2 bv = d_w2frag[k2 * 32 + lane];
        mma16816(d0, d1, d2, d3, A0, A1, A2, A3, bv.x, bv.y);
    }

    // ---- masked output: d0,d1 = row g cols 2q,2q+1; d2,d3 = row g+8 ----
    {
        int r0c = 2 * q, r1c = 2 * q + 1;
        float b2v0 = b2[r0c];                       // r0c in {0,2,4,6} < 7
        float b2v1 = (r1c < RR) ? b2[r1c] : 0.f;
#pragma unroll
        for (int half = 0; half < 2; half++) {
            int m = g + half * 8;
            float v0 = half ? d2 : d0;
            float v1 = half ? d3 : d1;
            int occ = __shfl_sync(~0u, nd, m) >= 0;
            int bb2 = b0w + (m >> 3);
            int orow = bb2 * (GG * RR) + (m & 7) * RR;
            out[orow + r0c] = (occ && mvm[orow + r0c] != 0) ? v0 + b2v0 : NEGV;
            if (r1c < RR)
                out[orow + r1c] = (occ && mvm[orow + r1c] != 0) ? v1 + b2v1 : NEGV;
        }
    }
}

// ---------------- launch ---------------------------------------------------
extern "C" void kernel_launch(void* const* d_in, const int* in_sizes, int n_in,
                              void* d_out, int out_size) {
    const float* nf    = (const float*)d_in[0];
    const float* gf    = (const float*)d_in[1];
    const int*   gmask = (const int*)d_in[2];
    const int*   mvm   = (const int*)d_in[3];
    const int*   batch = (const int*)d_in[4];
    const float* w1    = (const float*)d_in[5];
    const float* b1    = (const float*)d_in[6];
    const float* w2    = (const float*)d_in[7];
    const float* b2    = (const float*)d_in[8];
    float*       out   = (float*)d_out;

    cudaFuncSetAttribute(k_main, cudaFuncAttributeMaxDynamicSharedMemorySize,
                         MAIN_SMEM_BYTES);

    k_front<<<FGRID, 256>>>(gmask, batch, w1, w2, b1, gf);
    k_main<<<512, 128, MAIN_SMEM_BYTES>>>(nf, b2, mvm, out);
}